// round 16
// baseline (speedup 1.0000x reference)
#include <cuda_runtime.h>
#include <cuda_bf16.h>
#include <math.h>

#define SEQ 4096
#define DM  768
#define NH  12
#define HD  64

typedef unsigned int u32;

__device__ __forceinline__ u32 f2tf(float f) {
    u32 u; asm("cvt.rna.tf32.f32 %0, %1;" : "=r"(u) : "f"(f)); return u;
}
__device__ __forceinline__ float f2tff(float f) { return __uint_as_float(f2tf(f)); }

__device__ __forceinline__ float ex2(float x) {
    float y; asm("ex2.approx.f32 %0, %1;" : "=f"(y) : "f"(x)); return y;
}

#define MMA_TF32(d, a0, a1, a2, a3, b0, b1)                                        \
    asm volatile(                                                                  \
        "mma.sync.aligned.m16n8k8.row.col.f32.tf32.tf32.f32 "                      \
        "{%0,%1,%2,%3},{%4,%5,%6,%7},{%8,%9},{%0,%1,%2,%3};"                       \
        : "+f"((d)[0]), "+f"((d)[1]), "+f"((d)[2]), "+f"((d)[3])                   \
        : "r"(a0), "r"(a1), "r"(a2), "r"(a3), "r"(b0), "r"(b1))

__device__ __forceinline__ void ldsm4(u32& r0, u32& r1, u32& r2, u32& r3, u32 addr) {
    asm volatile("ldmatrix.sync.aligned.m8n8.x4.shared.b16 {%0,%1,%2,%3}, [%4];"
                 : "=r"(r0), "=r"(r1), "=r"(r2), "=r"(r3) : "r"(addr));
}

__device__ __forceinline__ u32 smaddr(const void* p) {
    return (u32)__cvta_generic_to_shared(p);
}

#define CP16(sm, gm) \
    asm volatile("cp.async.cg.shared.global [%0], [%1], 16;" :: "r"(sm), "l"(gm))
#define CP_COMMIT() asm volatile("cp.async.commit_group;")
#define CP_WAIT0()  asm volatile("cp.async.wait_group 0;")
#define CP_WAIT1()  asm volatile("cp.async.wait_group 1;")

// Scratch (tf32-rounded at producers). Weights stored TRANSPOSED [n][k].
__device__ float g_x[SEQ * DM];
__device__ float g_wqt[DM * DM];
__device__ float g_wkt[DM * DM];
__device__ float g_wvt[DM * DM];
__device__ float g_wot[DM * DM];
__device__ float g_q[SEQ * DM];
__device__ float g_k[SEQ * DM];
__device__ float g_v[SEQ * DM];
__device__ float g_ctx[SEQ * DM];
// Split-K flash partials: 12 heads x 16 qb x 2 splits
__device__ float g_po[12 * 16 * 2 * 128 * 64];
__device__ float g_pml[12 * 16 * 2 * 256];

#define QSCALE 0.18033688011112042f   // 0.125 * log2(e)

// ---------------------------------------------------------------------------
// Prep 1: round x  (fp32 -> tf32 copy)
// ---------------------------------------------------------------------------
#define NX4 (SEQ * DM / 4)

__global__ __launch_bounds__(256) void round_x_kernel(const float* __restrict__ x) {
    const int i = blockIdx.x * 256 + threadIdx.x;
    if (i >= NX4) return;
    float4 v = ((const float4*)x)[i];
    v.x = f2tff(v.x); v.y = f2tff(v.y); v.z = f2tff(v.z); v.w = f2tff(v.w);
    ((float4*)g_x)[i] = v;
}

// ---------------------------------------------------------------------------
// Prep 2: transpose + round all four weights: w[k][n] -> wT[n][k] (tf32)
// grid (24, 24, 4), block 256 (32x8)
// ---------------------------------------------------------------------------
__global__ __launch_bounds__(256) void transpose_w_kernel(
    const float* __restrict__ wq, const float* __restrict__ wk,
    const float* __restrict__ wv, const float* __restrict__ wo) {
    __shared__ float t[32][33];
    const float* src;
    float* dst;
    switch (blockIdx.z) {
        case 0: src = wq; dst = g_wqt; break;
        case 1: src = wk; dst = g_wkt; break;
        case 2: src = wv; dst = g_wvt; break;
        default: src = wo; dst = g_wot; break;
    }
    const int tx = threadIdx.x & 31;
    const int ty = threadIdx.x >> 5;
    const int k0 = blockIdx.x * 32;
    const int n0 = blockIdx.y * 32;
#pragma unroll
    for (int j = 0; j < 4; j++)
        t[ty + j * 8][tx] = src[(size_t)(k0 + ty + j * 8) * DM + n0 + tx];
    __syncthreads();
#pragma unroll
    for (int j = 0; j < 4; j++)
        dst[(size_t)(n0 + ty + j * 8) * DM + k0 + tx] = f2tff(t[tx][ty + j * 8]);
}

// ---------------------------------------------------------------------------
// 128x128x32 GEMM, tf32 mma, cp.async double-buffered, ALL-LDSM fragments.
// A [m][k] stride 36; B (transposed weights) [n][k] stride 36.
// 8 warps, warp = 32m x 64n. MODE: 1 = tf32-rounded out, 2 = rounded * QSCALE
// ---------------------------------------------------------------------------
#define TS_STR 36
#define GEMM_BUF (128 * TS_STR * 2)
#define GEMM_SMEM (2 * GEMM_BUF * 4)
#define NKT (DM / 32)

__device__ __forceinline__ void gemm_issue(const float* __restrict__ A,
                                           const float* __restrict__ BT,
                                           float* As, float* Bs,
                                           int m0, int n0, int k0, int tid) {
#pragma unroll
    for (int t = 0; t < 4; t++) {
        const int idx = tid + t * 256;
        const int r = idx >> 3;
        const int kq = (idx & 7) * 4;
        CP16(smaddr(&As[r * TS_STR + kq]), A  + (size_t)(m0 + r) * DM + k0 + kq);
        CP16(smaddr(&Bs[r * TS_STR + kq]), BT + (size_t)(n0 + r) * DM + k0 + kq);
    }
}

template <int MODE>
__device__ __forceinline__ void gemm_mma(const float* __restrict__ A,
                                         const float* __restrict__ BT,
                                         float* __restrict__ C) {
    extern __shared__ float gsm[];
    float* As[2] = {gsm, gsm + GEMM_BUF};
    float* Bs[2] = {gsm + 128 * TS_STR, gsm + GEMM_BUF + 128 * TS_STR};

    const int tid = threadIdx.x;
    const int lane = tid & 31;
    const int wid = tid >> 5;
    const int gid = lane >> 2;
    const int tig = lane & 3;
    const int wm = wid >> 1;
    const int wn = wid & 1;
    const int m0 = blockIdx.y * 128;
    const int n0 = blockIdx.x * 128;

    // LDSM lane-address offsets (bytes)
    const u32 a_off = (u32)(((wm * 32 + (lane & 15)) * TS_STR + (lane >> 4) * 4) * 4);
    const int brow = (lane & 7) + ((lane & 16) >> 1);
    const int bcol = (lane & 8) >> 1;
    const u32 b_off = (u32)(((wn * 64 + brow) * TS_STR + bcol) * 4);

    float c[2][8][4];
#pragma unroll
    for (int i = 0; i < 2; i++)
#pragma unroll
        for (int f = 0; f < 8; f++)
#pragma unroll
            for (int j = 0; j < 4; j++) c[i][f][j] = 0.f;

    gemm_issue(A, BT, As[0], Bs[0], m0, n0, 0, tid);
    CP_COMMIT();

    for (int t = 0; t < NKT; t++) {
        const int cur = t & 1;
        if (t + 1 < NKT) {
            gemm_issue(A, BT, As[cur ^ 1], Bs[cur ^ 1], m0, n0, (t + 1) * 32, tid);
            CP_COMMIT();
            CP_WAIT1();
        } else {
            CP_WAIT0();
        }
        __syncthreads();

        const u32 a_base = smaddr(As[cur]) + a_off;
        const u32 b_base = smaddr(Bs[cur]) + b_off;
#pragma unroll
        for (int k8 = 0; k8 < 4; k8++) {
            u32 aA0, aA1, aA2, aA3, aB0, aB1, aB2, aB3;
            ldsm4(aA0, aA1, aA2, aA3, a_base + k8 * 32);
            ldsm4(aB0, aB1, aB2, aB3, a_base + 16 * TS_STR * 4 + k8 * 32);
#pragma unroll
            for (int fp = 0; fp < 4; fp++) {
                u32 b0, b1, b2, b3;
                ldsm4(b0, b1, b2, b3, b_base + fp * (16 * TS_STR * 4) + k8 * 32);
                MMA_TF32(c[0][2 * fp],     aA0, aA1, aA2, aA3, b0, b1);
                MMA_TF32(c[0][2 * fp + 1], aA0, aA1, aA2, aA3, b2, b3);
                MMA_TF32(c[1][2 * fp],     aB0, aB1, aB2, aB3, b0, b1);
                MMA_TF32(c[1][2 * fp + 1], aB0, aB1, aB2, aB3, b2, b3);
            }
        }
        __syncthreads();
    }

#pragma unroll
    for (int fm = 0; fm < 2; fm++) {
        const int r1 = m0 + wm * 32 + fm * 16 + gid;
#pragma unroll
        for (int f = 0; f < 8; f++) {
            const int n = n0 + wn * 64 + f * 8 + 2 * tig;
            float v[4] = {c[fm][f][0], c[fm][f][1], c[fm][f][2], c[fm][f][3]};
            if (MODE == 1) {
#pragma unroll
                for (int j = 0; j < 4; j++) v[j] = f2tff(v[j]);
            } else {
#pragma unroll
                for (int j = 0; j < 4; j++) v[j] = f2tff(v[j] * QSCALE);
            }
            *(float2*)(C + (size_t)r1 * DM + n)       = make_float2(v[0], v[1]);
            *(float2*)(C + (size_t)(r1 + 8) * DM + n) = make_float2(v[2], v[3]);
        }
    }
}

__global__ __launch_bounds__(256, 2) void qkv_kernel() {
    if (blockIdx.z == 0)      gemm_mma<2>(g_x, g_wqt, g_q);
    else if (blockIdx.z == 1) gemm_mma<1>(g_x, g_wkt, g_k);
    else                      gemm_mma<1>(g_x, g_wvt, g_v);
}

// ---------------------------------------------------------------------------
// 64x128x32 GEMM (out projection), all-LDSM, 384 CTAs.
// 8 warps: wm = wid>>1 (16 rows), wn = wid&1 (64 cols).
// ---------------------------------------------------------------------------
#define G64_BUF ((64 + 128) * TS_STR)
#define G64_SMEM (2 * G64_BUF * 4)

__device__ __forceinline__ void gemm64_issue(const float* __restrict__ A,
                                             const float* __restrict__ BT,
                                             float* As, float* Bs,
                                             int m0, int n0, int k0, int tid) {
#pragma unroll
    for (int t = 0; t < 2; t++) {
        const int idx = tid + t * 256;
        const int r = idx >> 3;
        const int kq = (idx & 7) * 4;
        CP16(smaddr(&As[r * TS_STR + kq]), A + (size_t)(m0 + r) * DM + k0 + kq);
    }
#pragma unroll
    for (int t = 0; t < 4; t++) {
        const int idx = tid + t * 256;
        const int r = idx >> 3;
        const int kq = (idx & 7) * 4;
        CP16(smaddr(&Bs[r * TS_STR + kq]), BT + (size_t)(n0 + r) * DM + k0 + kq);
    }
}

__global__ __launch_bounds__(256, 2) void out_proj_kernel(const float* __restrict__ bo,
                                                          float* __restrict__ out) {
    extern __shared__ float gsm[];
    float* As[2] = {gsm, gsm + G64_BUF};
    float* Bs[2] = {gsm + 64 * TS_STR, gsm + G64_BUF + 64 * TS_STR};

    const int tid = threadIdx.x;
    const int lane = tid & 31;
    const int wid = tid >> 5;
    const int gid = lane >> 2;
    const int tig = lane & 3;
    const int wm = wid >> 1;
    const int wn = wid & 1;
    const int m0 = blockIdx.y * 64;
    const int n0 = blockIdx.x * 128;

    const u32 a_off = (u32)(((wm * 16 + (lane & 15)) * TS_STR + (lane >> 4) * 4) * 4);
    const int brow = (lane & 7) + ((lane & 16) >> 1);
    const int bcol = (lane & 8) >> 1;
    const u32 b_off = (u32)(((wn * 64 + brow) * TS_STR + bcol) * 4);

    float c[8][4];
#pragma unroll
    for (int f = 0; f < 8; f++)
#pragma unroll
        for (int j = 0; j < 4; j++) c[f][j] = 0.f;

    gemm64_issue(g_ctx, g_wot, As[0], Bs[0], m0, n0, 0, tid);
    CP_COMMIT();

    for (int t = 0; t < NKT; t++) {
        const int cur = t & 1;
        if (t + 1 < NKT) {
            gemm64_issue(g_ctx, g_wot, As[cur ^ 1], Bs[cur ^ 1], m0, n0, (t + 1) * 32, tid);
            CP_COMMIT();
            CP_WAIT1();
        } else {
            CP_WAIT0();
        }
        __syncthreads();

        const u32 a_base = smaddr(As[cur]) + a_off;
        const u32 b_base = smaddr(Bs[cur]) + b_off;
#pragma unroll
        for (int k8 = 0; k8 < 4; k8++) {
            u32 a0, a1, a2, a3;
            ldsm4(a0, a1, a2, a3, a_base + k8 * 32);
#pragma unroll
            for (int fp = 0; fp < 4; fp++) {
                u32 b0, b1, b2, b3;
                ldsm4(b0, b1, b2, b3, b_base + fp * (16 * TS_STR * 4) + k8 * 32);
                MMA_TF32(c[2 * fp],     a0, a1, a2, a3, b0, b1);
                MMA_TF32(c[2 * fp + 1], a0, a1, a2, a3, b2, b3);
            }
        }
        __syncthreads();
    }

    const int r1 = m0 + wm * 16 + gid;
#pragma unroll
    for (int f = 0; f < 8; f++) {
        const int n = n0 + wn * 64 + f * 8 + 2 * tig;
        const float b0 = bo[n], b1 = bo[n + 1];
        *(float2*)(out + (size_t)r1 * DM + n)       = make_float2(c[f][0] + b0, c[f][1] + b1);
        *(float2*)(out + (size_t)(r1 + 8) * DM + n) = make_float2(c[f][2] + b0, c[f][3] + b1);
    }
}

// ---------------------------------------------------------------------------
// Flash attention (causal), tf32 mma, register-resident P, split-K.
// (unchanged from round 15)
// ---------------------------------------------------------------------------
#define QS_STR 68
#define KS_STR 68
#define VS_STR 68
#define FLASH_SMEM ((128 * QS_STR + 128 * KS_STR + 128 * VS_STR) * 4)

__global__ __launch_bounds__(256, 2) void flash_kernel() {
    extern __shared__ float smf[];
    float* Qs = smf;
    float* Ks = Qs + 128 * QS_STR;
    float* Vs = Ks + 128 * KS_STR;

    const int tid = threadIdx.x;
    const int lane = tid & 31;
    const int wid = tid >> 5;
    const int gid = lane >> 2;
    const int tig = lane & 3;
    const int rw = wid * 16;
    const int h = blockIdx.y;

    const int u = blockIdx.x;
    int qb, split, nsp;
    if (u < 32) { qb = 31 - (u >> 1); split = u & 1; nsp = 2; }
    else        { qb = 47 - u;        split = 0;     nsp = 1; }
    const int nk = qb + 1;
    const int h1 = (nk + 1) >> 1;
    const int kb_lo = (nsp == 2 && split == 1) ? h1 : 0;
    const int kb_hi = (nsp == 2 && split == 0) ? h1 : nk;
    const int q0 = qb * 128;

    const int arow = rw + (lane & 15);
    const int acol = (lane >> 4) * 4;
    const int brow = (lane & 7) + ((lane & 16) >> 1);
    const int bcol = (lane & 8) >> 1;
    const u32 q_a = smaddr(&Qs[arow * QS_STR + acol]);
    const u32 k_b = smaddr(&Ks[brow * KS_STR + bcol]);

#pragma unroll
    for (int t = 0; t < 8; t++) {
        const int idx = tid + t * 256;
        const int r = idx >> 4;
        const int d4 = (idx & 15) * 4;
        CP16(smaddr(&Qs[r * QS_STR + d4]),
             g_q + (size_t)(q0 + r) * DM + h * HD + d4);
    }

    const int row1 = q0 + rw + gid;
    const int row2 = row1 + 8;
    float m1 = -1e30f, m2 = -1e30f, l1 = 0.f, l2 = 0.f;
    float o[8][4];
#pragma unroll
    for (int f = 0; f < 8; f++)
#pragma unroll
        for (int j = 0; j < 4; j++) o[f][j] = 0.f;

    for (int kb = kb_lo; kb < kb_hi; kb++) {
        const int k0g = kb * 128;
        __syncthreads();

#pragma unroll
        for (int t = 0; t < 8; t++) {
            const int idx = tid + t * 256;
            const int r = idx >> 4;
            const int d4 = (idx & 15) * 4;
            CP16(smaddr(&Ks[r * KS_STR + d4]),
                 g_k + (size_t)(k0g + r) * DM + h * HD + d4);
            CP16(smaddr(&Vs[r * VS_STR + d4]),
                 g_v + (size_t)(k0g + r) * DM + h * HD + d4);
        }
        CP_COMMIT();
        CP_WAIT0();
        __syncthreads();

        float s[16][4];
#pragma unroll
        for (int f = 0; f < 16; f++)
#pragma unroll
            for (int j = 0; j < 4; j++) s[f][j] = 0.f;

#pragma unroll
        for (int d8 = 0; d8 < 8; d8++) {
            u32 a0, a1, a2, a3;
            ldsm4(a0, a1, a2, a3, q_a + d8 * 32);
#pragma unroll
            for (int fp = 0; fp < 8; fp++) {
                u32 b0, b1, b2, b3;
                ldsm4(b0, b1, b2, b3, k_b + fp * (16 * KS_STR * 4) + d8 * 32);
                MMA_TF32(s[2 * fp],     a0, a1, a2, a3, b0, b1);
                MMA_TF32(s[2 * fp + 1], a0, a1, a2, a3, b2, b3);
            }
        }

        if (kb == qb) {
#pragma unroll
            for (int f = 0; f < 16; f++) {
                const int cb = k0g + f * 8 + 2 * tig;
                if (cb     > row1) s[f][0] = -1e30f;
                if (cb + 1 > row1) s[f][1] = -1e30f;
                if (cb     > row2) s[f][2] = -1e30f;
                if (cb + 1 > row2) s[f][3] = -1e30f;
            }
        }

        float mx1 = -1e30f, mx2 = -1e30f;
#pragma unroll
        for (int f = 0; f < 16; f++) {
            mx1 = fmaxf(mx1, fmaxf(s[f][0], s[f][1]));
            mx2 = fmaxf(mx2, fmaxf(s[f][2], s[f][3]));
        }
#pragma unroll
        for (int off = 1; off <= 2; off <<= 1) {
            mx1 = fmaxf(mx1, __shfl_xor_sync(0xffffffffu, mx1, off));
            mx2 = fmaxf(mx2, __shfl_xor_sync(0xffffffffu, mx2, off));
        }
        const float mn1 = fmaxf(m1, mx1);
        const float mn2 = fmaxf(m2, mx2);
        float rs1 = 0.f, rs2 = 0.f;
#pragma unroll
        for (int f = 0; f < 16; f++) {
            s[f][0] = ex2(s[f][0] - mn1);
            s[f][1] = ex2(s[f][1] - mn1);
            s[f][2] = ex2(s[f][2] - mn2);
            s[f][3] = ex2(s[f][3] - mn2);
            rs1 += s[f][0] + s[f][1];
            rs2 += s[f][2] + s[f][3];
        }
#pragma unroll
        for (int off = 1; off <= 2; off <<= 1) {
            rs1 += __shfl_xor_sync(0xffffffffu, rs1, off);
            rs2 += __shfl_xor_sync(0xffffffffu, rs2, off);
        }
        const float al1 = ex2(m1 - mn1);
        const float al2 = ex2(m2 - mn2);
        m1 = mn1; m2 = mn2;
        l1 = l1 * al1 + rs1;
        l2 = l2 * al2 + rs2;
#pragma unroll
        for (int f = 0; f < 8; f++) {
            o[f][0] *= al1; o[f][1] *= al1;
            o[f][2] *= al2; o[f][3] *= al2;
        }

#pragma unroll
        for (int k8 = 0; k8 < 16; k8++) {
            const u32 a0 = f2tf(s[k8][0]);
            const u32 a1 = f2tf(s[k8][2]);
            const u32 a2 = f2tf(s[k8][1]);
            const u32 a3 = f2tf(s[k8][3]);
            const float* vr0 = &Vs[(k8 * 8 + 2 * tig) * VS_STR];
            const float* vr1 = vr0 + VS_STR;
#pragma unroll
            for (int f = 0; f < 8; f++) {
                const u32 b0 = __float_as_uint(vr0[f * 8 + gid]);
                const u32 b1 = __float_as_uint(vr1[f * 8 + gid]);
                MMA_TF32(o[f], a0, a1, a2, a3, b0, b1);
            }
        }
    }

    if (nsp == 1) {
        const float inv1 = 1.0f / l1;
        const float inv2 = 1.0f / l2;
#pragma unroll
        for (int f = 0; f < 8; f++) {
            const int d = h * HD + f * 8 + 2 * tig;
            *(float2*)(g_ctx + (size_t)(q0 + rw + gid) * DM + d) =
                make_float2(f2tff(o[f][0] * inv1), f2tff(o[f][1] * inv1));
            *(float2*)(g_ctx + (size_t)(q0 + rw + gid + 8) * DM + d) =
                make_float2(f2tff(o[f][2] * inv2), f2tff(o[f][3] * inv2));
        }
    } else {
        const int p = (h * 16 + (qb - 16)) * 2 + split;
        float* po = g_po + (size_t)p * 8192;
        float* pml = g_pml + (size_t)p * 256;
#pragma unroll
        for (int f = 0; f < 8; f++) {
            const int d = f * 8 + 2 * tig;
            *(float2*)&po[(rw + gid) * 64 + d]     = make_float2(o[f][0], o[f][1]);
            *(float2*)&po[(rw + gid + 8) * 64 + d] = make_float2(o[f][2], o[f][3]);
        }
        if (tig == 0) {
            pml[rw + gid]           = m1;
            pml[128 + rw + gid]     = l1;
            pml[rw + gid + 8]       = m2;
            pml[128 + rw + gid + 8] = l2;
        }
    }
}

// ---------------------------------------------------------------------------
// Merge split-K partials. grid (32, 12): block = half of one (qb,h) tile.
// ---------------------------------------------------------------------------
__global__ __launch_bounds__(256) void merge_kernel() {
    const int qb = 16 + (blockIdx.x >> 1);
    const int half = blockIdx.x & 1;
    const int h = blockIdx.y;
    const int pb = (h * 16 + (qb - 16)) * 2;
    const float* o0 = g_po + (size_t)pb * 8192;
    const float* o1 = o0 + 8192;
    const float* ml0 = g_pml + (size_t)pb * 256;
    const float* ml1 = ml0 + 256;

    const int t = threadIdx.x;
    const int r = half * 64 + (t >> 2);    // 64 rows per block
    const int d0 = (t & 3) * 16;           // 16 floats per thread

    const float m0 = ml0[r], la = ml0[128 + r];
    const float m1 = ml1[r], lb = ml1[128 + r];
    const float m = fmaxf(m0, m1);
    const float w0 = ex2(m0 - m);
    const float w1 = ex2(m1 - m);
    const float linv = 1.0f / (la * w0 + lb * w1);

    float* dst = g_ctx + (size_t)(qb * 128 + r) * DM + h * HD + d0;
#pragma unroll
    for (int j = 0; j < 4; j++) {
        const float4 a = *(const float4*)&o0[r * 64 + d0 + j * 4];
        const float4 b = *(const float4*)&o1[r * 64 + d0 + j * 4];
        float4 v;
        v.x = f2tff((a.x * w0 + b.x * w1) * linv);
        v.y = f2tff((a.y * w0 + b.y * w1) * linv);
        v.z = f2tff((a.z * w0 + b.z * w1) * linv);
        v.w = f2tff((a.w * w0 + b.w * w1) * linv);
        *(float4*)(dst + j * 4) = v;
    }
}

// ---------------------------------------------------------------------------
extern "C" void kernel_launch(void* const* d_in, const int* in_sizes, int n_in,
                              void* d_out, int out_size) {
    const float* x  = (const float*)d_in[0];
    const float* wq = (const float*)d_in[1];
    const float* wk = (const float*)d_in[2];
    const float* wv = (const float*)d_in[3];
    const float* wo = (const float*)d_in[4];
    const float* bo = (const float*)d_in[5];
    float* out = (float*)d_out;

    cudaFuncSetAttribute(flash_kernel, cudaFuncAttributeMaxDynamicSharedMemorySize,
                         FLASH_SMEM);
    cudaFuncSetAttribute(qkv_kernel, cudaFuncAttributeMaxDynamicSharedMemorySize,
                         GEMM_SMEM);
    cudaFuncSetAttribute(out_proj_kernel, cudaFuncAttributeMaxDynamicSharedMemorySize,
                         G64_SMEM);

    round_x_kernel<<<(NX4 + 255) / 256, 256>>>(x);
    transpose_w_kernel<<<dim3(DM / 32, DM / 32, 4), 256>>>(wq, wk, wv, wo);
    qkv_kernel<<<dim3(DM / 128, SEQ / 128, 3), 256, GEMM_SMEM>>>();
    flash_kernel<<<dim3(48, NH), 256, FLASH_SMEM>>>();
    merge_kernel<<<dim3(32, NH), 256>>>();
    out_proj_kernel<<<dim3(DM / 128, SEQ / 64), 256, G64_SMEM>>>(bo, out);
}

// round 17
// speedup vs baseline: 1.4620x; 1.4620x over previous
#include <cuda_runtime.h>
#include <cuda_bf16.h>
#include <math.h>

#define SEQ 4096
#define DM  768
#define NH  12
#define HD  64

typedef unsigned int u32;

__device__ __forceinline__ u32 f2tf(float f) {
    u32 u; asm("cvt.rna.tf32.f32 %0, %1;" : "=r"(u) : "f"(f)); return u;
}
__device__ __forceinline__ float f2tff(float f) { return __uint_as_float(f2tf(f)); }

__device__ __forceinline__ float ex2(float x) {
    float y; asm("ex2.approx.f32 %0, %1;" : "=f"(y) : "f"(x)); return y;
}

#define MMA_TF32(d, a0, a1, a2, a3, b0, b1)                                        \
    asm volatile(                                                                  \
        "mma.sync.aligned.m16n8k8.row.col.f32.tf32.tf32.f32 "                      \
        "{%0,%1,%2,%3},{%4,%5,%6,%7},{%8,%9},{%0,%1,%2,%3};"                       \
        : "+f"((d)[0]), "+f"((d)[1]), "+f"((d)[2]), "+f"((d)[3])                   \
        : "r"(a0), "r"(a1), "r"(a2), "r"(a3), "r"(b0), "r"(b1))

__device__ __forceinline__ void ldsm4(u32& r0, u32& r1, u32& r2, u32& r3, u32 addr) {
    asm volatile("ldmatrix.sync.aligned.m8n8.x4.shared.b16 {%0,%1,%2,%3}, [%4];"
                 : "=r"(r0), "=r"(r1), "=r"(r2), "=r"(r3) : "r"(addr));
}

__device__ __forceinline__ u32 smaddr(const void* p) {
    return (u32)__cvta_generic_to_shared(p);
}

#define CP16(sm, gm) \
    asm volatile("cp.async.cg.shared.global [%0], [%1], 16;" :: "r"(sm), "l"(gm))
#define CP_COMMIT() asm volatile("cp.async.commit_group;")
#define CP_WAIT0()  asm volatile("cp.async.wait_group 0;")
#define CP_WAIT1()  asm volatile("cp.async.wait_group 1;")

// Scratch (tf32-rounded at producers)
__device__ float g_x[SEQ * DM];
__device__ float g_wq[DM * DM];
__device__ float g_wk[DM * DM];
__device__ float g_wv[DM * DM];
__device__ float g_wo[DM * DM];
__device__ float g_q[SEQ * DM];
__device__ float g_k[SEQ * DM];
__device__ float g_v[SEQ * DM];
__device__ float g_ctx[SEQ * DM];
// Split-K flash partials: 12 heads x 16 qb x 2 splits
__device__ float g_po[12 * 16 * 2 * 128 * 64];
__device__ float g_pml[12 * 16 * 2 * 256];

#define QSCALE 0.18033688011112042f   // 0.125 * log2(e)

// ---------------------------------------------------------------------------
// Fused pre-round fp32 -> tf32 of x + all four weight matrices, ONE launch.
// ---------------------------------------------------------------------------
#define NX4 (SEQ * DM / 4)
#define NW4 (DM * DM / 4)
#define NTOT4 (NX4 + 4 * NW4)

__global__ __launch_bounds__(256) void round_all_kernel(
    const float* __restrict__ x,  const float* __restrict__ wq,
    const float* __restrict__ wk, const float* __restrict__ wv,
    const float* __restrict__ wo) {
    const int i = blockIdx.x * 256 + threadIdx.x;
    if (i >= NTOT4) return;
    const float4* src;
    float4* dst;
    int j;
    if (i < NX4) {
        src = (const float4*)x; dst = (float4*)g_x; j = i;
    } else {
        const int t = i - NX4;
        const int w = t / NW4;
        j = t - w * NW4;
        if (w == 0)      { src = (const float4*)wq; dst = (float4*)g_wq; }
        else if (w == 1) { src = (const float4*)wk; dst = (float4*)g_wk; }
        else if (w == 2) { src = (const float4*)wv; dst = (float4*)g_wv; }
        else             { src = (const float4*)wo; dst = (float4*)g_wo; }
    }
    float4 v = src[j];
    v.x = f2tff(v.x); v.y = f2tff(v.y); v.z = f2tff(v.z); v.w = f2tff(v.w);
    dst[j] = v;
}

// ---------------------------------------------------------------------------
// 128x128x32 GEMM via mma.sync tf32, cp.async double-buffered.
// MODE: 1 = write tf32-rounded, 2 = rounded * QSCALE
// ---------------------------------------------------------------------------
#define AS_STR 36
#define BS_STR 136
#define GEMM_BUF (128 * AS_STR + 32 * BS_STR)
#define GEMM_SMEM (2 * GEMM_BUF * 4)
#define NKT (DM / 32)

__device__ __forceinline__ void gemm_issue(const float* __restrict__ A,
                                           const float* __restrict__ B,
                                           float* As, float* Bs,
                                           int m0, int n0, int k0, int tid) {
#pragma unroll
    for (int t = 0; t < 4; t++) {
        const int idx = tid + t * 256;
        const int m = idx >> 3;
        const int kq = (idx & 7) * 4;
        CP16(smaddr(&As[m * AS_STR + kq]), A + (size_t)(m0 + m) * DM + k0 + kq);
        const int kb = idx >> 5;
        const int nb = (idx & 31) * 4;
        CP16(smaddr(&Bs[kb * BS_STR + nb]), B + (size_t)(k0 + kb) * DM + n0 + nb);
    }
}

template <int MODE>
__device__ __forceinline__ void gemm_mma(const float* __restrict__ A,
                                         const float* __restrict__ B,
                                         float* __restrict__ C) {
    extern __shared__ float gsm[];
    float* As[2] = {gsm, gsm + GEMM_BUF};
    float* Bs[2] = {gsm + 128 * AS_STR, gsm + GEMM_BUF + 128 * AS_STR};

    const int tid = threadIdx.x;
    const int lane = tid & 31;
    const int wid = tid >> 5;
    const int gid = lane >> 2;
    const int tig = lane & 3;
    const int wm = wid >> 1;
    const int wn = wid & 1;
    const int m0 = blockIdx.y * 128;
    const int n0 = blockIdx.x * 128;

    float c[2][8][4];
#pragma unroll
    for (int i = 0; i < 2; i++)
#pragma unroll
        for (int f = 0; f < 8; f++)
#pragma unroll
            for (int j = 0; j < 4; j++) c[i][f][j] = 0.f;

    gemm_issue(A, B, As[0], Bs[0], m0, n0, 0, tid);
    CP_COMMIT();

    for (int t = 0; t < NKT; t++) {
        const int cur = t & 1;
        if (t + 1 < NKT) {
            gemm_issue(A, B, As[cur ^ 1], Bs[cur ^ 1], m0, n0, (t + 1) * 32, tid);
            CP_COMMIT();
            CP_WAIT1();
        } else {
            CP_WAIT0();
        }
        __syncthreads();

        const float* Ac = As[cur];
        const float* Bc = Bs[cur];
#pragma unroll
        for (int k8 = 0; k8 < 4; k8++) {
            u32 a0[2], a1[2], a2[2], a3[2];
#pragma unroll
            for (int fm = 0; fm < 2; fm++) {
                const int rb = wm * 32 + fm * 16;
                const int kc = k8 * 8 + tig;
                a0[fm] = __float_as_uint(Ac[(rb + gid)     * AS_STR + kc]);
                a1[fm] = __float_as_uint(Ac[(rb + gid + 8) * AS_STR + kc]);
                a2[fm] = __float_as_uint(Ac[(rb + gid)     * AS_STR + kc + 4]);
                a3[fm] = __float_as_uint(Ac[(rb + gid + 8) * AS_STR + kc + 4]);
            }
#pragma unroll
            for (int f = 0; f < 8; f++) {
                const int nc = wn * 64 + f * 8 + gid;
                const u32 b0 = __float_as_uint(Bc[(k8 * 8 + tig)     * BS_STR + nc]);
                const u32 b1 = __float_as_uint(Bc[(k8 * 8 + tig + 4) * BS_STR + nc]);
                MMA_TF32(c[0][f], a0[0], a1[0], a2[0], a3[0], b0, b1);
                MMA_TF32(c[1][f], a0[1], a1[1], a2[1], a3[1], b0, b1);
            }
        }
        __syncthreads();
    }

#pragma unroll
    for (int fm = 0; fm < 2; fm++) {
        const int r1 = m0 + wm * 32 + fm * 16 + gid;
#pragma unroll
        for (int f = 0; f < 8; f++) {
            const int n = n0 + wn * 64 + f * 8 + 2 * tig;
            float v[4] = {c[fm][f][0], c[fm][f][1], c[fm][f][2], c[fm][f][3]};
            if (MODE == 1) {
#pragma unroll
                for (int j = 0; j < 4; j++) v[j] = f2tff(v[j]);
            } else {
#pragma unroll
                for (int j = 0; j < 4; j++) v[j] = f2tff(v[j] * QSCALE);
            }
            *(float2*)(C + (size_t)r1 * DM + n)       = make_float2(v[0], v[1]);
            *(float2*)(C + (size_t)(r1 + 8) * DM + n) = make_float2(v[2], v[3]);
        }
    }
}

__global__ __launch_bounds__(256, 2) void qkv_kernel() {
    if (blockIdx.z == 0)      gemm_mma<2>(g_x, g_wq, g_q);
    else if (blockIdx.z == 1) gemm_mma<1>(g_x, g_wk, g_k);
    else                      gemm_mma<1>(g_x, g_wv, g_v);
}

// ---------------------------------------------------------------------------
// 64x128x32 GEMM (out projection): 384 CTAs for better wave packing.
// ---------------------------------------------------------------------------
#define G64_BUF (64 * AS_STR + 32 * BS_STR)
#define G64_SMEM (2 * G64_BUF * 4)

__device__ __forceinline__ void gemm64_issue(const float* __restrict__ A,
                                             const float* __restrict__ B,
                                             float* As, float* Bs,
                                             int m0, int n0, int k0, int tid) {
#pragma unroll
    for (int t = 0; t < 2; t++) {
        const int idx = tid + t * 256;
        const int m = idx >> 3;
        const int kq = (idx & 7) * 4;
        CP16(smaddr(&As[m * AS_STR + kq]), A + (size_t)(m0 + m) * DM + k0 + kq);
    }
#pragma unroll
    for (int t = 0; t < 4; t++) {
        const int idx = tid + t * 256;
        const int kb = idx >> 5;
        const int nb = (idx & 31) * 4;
        CP16(smaddr(&Bs[kb * BS_STR + nb]), B + (size_t)(k0 + kb) * DM + n0 + nb);
    }
}

__global__ __launch_bounds__(256, 2) void out_proj_kernel(const float* __restrict__ bo,
                                                          float* __restrict__ out) {
    extern __shared__ float gsm[];
    float* As[2] = {gsm, gsm + G64_BUF};
    float* Bs[2] = {gsm + 64 * AS_STR, gsm + G64_BUF + 64 * AS_STR};

    const int tid = threadIdx.x;
    const int lane = tid & 31;
    const int wid = tid >> 5;
    const int gid = lane >> 2;
    const int tig = lane & 3;
    const int wm = wid >> 1;        // 0..3 -> 16 rows each
    const int wn = wid & 1;         // 0..1 -> 64 cols each
    const int m0 = blockIdx.y * 64;
    const int n0 = blockIdx.x * 128;

    float c[8][4];
#pragma unroll
    for (int f = 0; f < 8; f++)
#pragma unroll
        for (int j = 0; j < 4; j++) c[f][j] = 0.f;

    gemm64_issue(g_ctx, g_wo, As[0], Bs[0], m0, n0, 0, tid);
    CP_COMMIT();

    for (int t = 0; t < NKT; t++) {
        const int cur = t & 1;
        if (t + 1 < NKT) {
            gemm64_issue(g_ctx, g_wo, As[cur ^ 1], Bs[cur ^ 1], m0, n0, (t + 1) * 32, tid);
            CP_COMMIT();
            CP_WAIT1();
        } else {
            CP_WAIT0();
        }
        __syncthreads();

        const float* Ac = As[cur];
        const float* Bc = Bs[cur];
#pragma unroll
        for (int k8 = 0; k8 < 4; k8++) {
            const int rb = wm * 16;
            const int kc = k8 * 8 + tig;
            const u32 a0 = __float_as_uint(Ac[(rb + gid)     * AS_STR + kc]);
            const u32 a1 = __float_as_uint(Ac[(rb + gid + 8) * AS_STR + kc]);
            const u32 a2 = __float_as_uint(Ac[(rb + gid)     * AS_STR + kc + 4]);
            const u32 a3 = __float_as_uint(Ac[(rb + gid + 8) * AS_STR + kc + 4]);
#pragma unroll
            for (int f = 0; f < 8; f++) {
                const int nc = wn * 64 + f * 8 + gid;
                const u32 b0 = __float_as_uint(Bc[(k8 * 8 + tig)     * BS_STR + nc]);
                const u32 b1 = __float_as_uint(Bc[(k8 * 8 + tig + 4) * BS_STR + nc]);
                MMA_TF32(c[f], a0, a1, a2, a3, b0, b1);
            }
        }
        __syncthreads();
    }

    const int r1 = m0 + wm * 16 + gid;
#pragma unroll
    for (int f = 0; f < 8; f++) {
        const int n = n0 + wn * 64 + f * 8 + 2 * tig;
        const float b0 = bo[n], b1 = bo[n + 1];
        *(float2*)(out + (size_t)r1 * DM + n)       = make_float2(c[f][0] + b0, c[f][1] + b1);
        *(float2*)(out + (size_t)(r1 + 8) * DM + n) = make_float2(c[f][2] + b0, c[f][3] + b1);
    }
}

// ---------------------------------------------------------------------------
// Flash attention (causal), tf32 mma, register-resident P, split-K.
// grid.x = 48 work units per head (LPT order); qb>=16 split into 2 halves.
// ---------------------------------------------------------------------------
#define QS_STR 68
#define KS_STR 68
#define VS_STR 68
#define FLASH_SMEM ((128 * QS_STR + 128 * KS_STR + 128 * VS_STR) * 4)

__global__ __launch_bounds__(256, 2) void flash_kernel() {
    extern __shared__ float smf[];
    float* Qs = smf;
    float* Ks = Qs + 128 * QS_STR;
    float* Vs = Ks + 128 * KS_STR;

    const int tid = threadIdx.x;
    const int lane = tid & 31;
    const int wid = tid >> 5;
    const int gid = lane >> 2;
    const int tig = lane & 3;
    const int rw = wid * 16;
    const int h = blockIdx.y;

    const int u = blockIdx.x;
    int qb, split, nsp;
    if (u < 32) { qb = 31 - (u >> 1); split = u & 1; nsp = 2; }
    else        { qb = 47 - u;        split = 0;     nsp = 1; }
    const int nk = qb + 1;
    const int h1 = (nk + 1) >> 1;
    const int kb_lo = (nsp == 2 && split == 1) ? h1 : 0;
    const int kb_hi = (nsp == 2 && split == 0) ? h1 : nk;
    const int q0 = qb * 128;

    const int arow = rw + (lane & 15);
    const int acol = (lane >> 4) * 4;
    const int brow = (lane & 7) + ((lane & 16) >> 1);
    const int bcol = (lane & 8) >> 1;
    const u32 q_a = smaddr(&Qs[arow * QS_STR + acol]);
    const u32 k_b = smaddr(&Ks[brow * KS_STR + bcol]);

#pragma unroll
    for (int t = 0; t < 8; t++) {
        const int idx = tid + t * 256;
        const int r = idx >> 4;
        const int d4 = (idx & 15) * 4;
        CP16(smaddr(&Qs[r * QS_STR + d4]),
             g_q + (size_t)(q0 + r) * DM + h * HD + d4);
    }

    const int row1 = q0 + rw + gid;
    const int row2 = row1 + 8;
    float m1 = -1e30f, m2 = -1e30f, l1 = 0.f, l2 = 0.f;
    float o[8][4];
#pragma unroll
    for (int f = 0; f < 8; f++)
#pragma unroll
        for (int j = 0; j < 4; j++) o[f][j] = 0.f;

    for (int kb = kb_lo; kb < kb_hi; kb++) {
        const int k0g = kb * 128;
        __syncthreads();

#pragma unroll
        for (int t = 0; t < 8; t++) {
            const int idx = tid + t * 256;
            const int r = idx >> 4;
            const int d4 = (idx & 15) * 4;
            CP16(smaddr(&Ks[r * KS_STR + d4]),
                 g_k + (size_t)(k0g + r) * DM + h * HD + d4);
            CP16(smaddr(&Vs[r * VS_STR + d4]),
                 g_v + (size_t)(k0g + r) * DM + h * HD + d4);
        }
        CP_COMMIT();
        CP_WAIT0();
        __syncthreads();

        float s[16][4];
#pragma unroll
        for (int f = 0; f < 16; f++)
#pragma unroll
            for (int j = 0; j < 4; j++) s[f][j] = 0.f;

#pragma unroll
        for (int d8 = 0; d8 < 8; d8++) {
            u32 a0, a1, a2, a3;
            ldsm4(a0, a1, a2, a3, q_a + d8 * 32);
#pragma unroll
            for (int fp = 0; fp < 8; fp++) {
                u32 b0, b1, b2, b3;
                ldsm4(b0, b1, b2, b3, k_b + fp * (16 * KS_STR * 4) + d8 * 32);
                MMA_TF32(s[2 * fp],     a0, a1, a2, a3, b0, b1);
                MMA_TF32(s[2 * fp + 1], a0, a1, a2, a3, b2, b3);
            }
        }

        if (kb == qb) {
#pragma unroll
            for (int f = 0; f < 16; f++) {
                const int cb = k0g + f * 8 + 2 * tig;
                if (cb     > row1) s[f][0] = -1e30f;
                if (cb + 1 > row1) s[f][1] = -1e30f;
                if (cb     > row2) s[f][2] = -1e30f;
                if (cb + 1 > row2) s[f][3] = -1e30f;
            }
        }

        float mx1 = -1e30f, mx2 = -1e30f;
#pragma unroll
        for (int f = 0; f < 16; f++) {
            mx1 = fmaxf(mx1, fmaxf(s[f][0], s[f][1]));
            mx2 = fmaxf(mx2, fmaxf(s[f][2], s[f][3]));
        }
#pragma unroll
        for (int off = 1; off <= 2; off <<= 1) {
            mx1 = fmaxf(mx1, __shfl_xor_sync(0xffffffffu, mx1, off));
            mx2 = fmaxf(mx2, __shfl_xor_sync(0xffffffffu, mx2, off));
        }
        const float mn1 = fmaxf(m1, mx1);
        const float mn2 = fmaxf(m2, mx2);
        float rs1 = 0.f, rs2 = 0.f;
#pragma unroll
        for (int f = 0; f < 16; f++) {
            s[f][0] = ex2(s[f][0] - mn1);
            s[f][1] = ex2(s[f][1] - mn1);
            s[f][2] = ex2(s[f][2] - mn2);
            s[f][3] = ex2(s[f][3] - mn2);
            rs1 += s[f][0] + s[f][1];
            rs2 += s[f][2] + s[f][3];
        }
#pragma unroll
        for (int off = 1; off <= 2; off <<= 1) {
            rs1 += __shfl_xor_sync(0xffffffffu, rs1, off);
            rs2 += __shfl_xor_sync(0xffffffffu, rs2, off);
        }
        const float al1 = ex2(m1 - mn1);
        const float al2 = ex2(m2 - mn2);
        m1 = mn1; m2 = mn2;
        l1 = l1 * al1 + rs1;
        l2 = l2 * al2 + rs2;
#pragma unroll
        for (int f = 0; f < 8; f++) {
            o[f][0] *= al1; o[f][1] *= al1;
            o[f][2] *= al2; o[f][3] *= al2;
        }

#pragma unroll
        for (int k8 = 0; k8 < 16; k8++) {
            const u32 a0 = f2tf(s[k8][0]);
            const u32 a1 = f2tf(s[k8][2]);
            const u32 a2 = f2tf(s[k8][1]);
            const u32 a3 = f2tf(s[k8][3]);
            const float* vr0 = &Vs[(k8 * 8 + 2 * tig) * VS_STR];
            const float* vr1 = vr0 + VS_STR;
#pragma unroll
            for (int f = 0; f < 8; f++) {
                const u32 b0 = __float_as_uint(vr0[f * 8 + gid]);
                const u32 b1 = __float_as_uint(vr1[f * 8 + gid]);
                MMA_TF32(o[f], a0, a1, a2, a3, b0, b1);
            }
        }
    }

    if (nsp == 1) {
        const float inv1 = 1.0f / l1;
        const float inv2 = 1.0f / l2;
#pragma unroll
        for (int f = 0; f < 8; f++) {
            const int d = h * HD + f * 8 + 2 * tig;
            *(float2*)(g_ctx + (size_t)(q0 + rw + gid) * DM + d) =
                make_float2(f2tff(o[f][0] * inv1), f2tff(o[f][1] * inv1));
            *(float2*)(g_ctx + (size_t)(q0 + rw + gid + 8) * DM + d) =
                make_float2(f2tff(o[f][2] * inv2), f2tff(o[f][3] * inv2));
        }
    } else {
        const int p = (h * 16 + (qb - 16)) * 2 + split;
        float* po = g_po + (size_t)p * 8192;
        float* pml = g_pml + (size_t)p * 256;
#pragma unroll
        for (int f = 0; f < 8; f++) {
            const int d = f * 8 + 2 * tig;
            *(float2*)&po[(rw + gid) * 64 + d]     = make_float2(o[f][0], o[f][1]);
            *(float2*)&po[(rw + gid + 8) * 64 + d] = make_float2(o[f][2], o[f][3]);
        }
        if (tig == 0) {
            pml[rw + gid]           = m1;
            pml[128 + rw + gid]     = l1;
            pml[rw + gid + 8]       = m2;
            pml[128 + rw + gid + 8] = l2;
        }
    }
}

// ---------------------------------------------------------------------------
// Merge split-K partials. grid (32, 12): each block = 64 rows of one (qb,h)
// tile; each thread handles 4 independent float4 pairs (ILP to hide latency).
// ---------------------------------------------------------------------------
__global__ __launch_bounds__(256) void merge_kernel() {
    const int qb = 16 + (blockIdx.x >> 1);
    const int half = blockIdx.x & 1;
    const int h = blockIdx.y;
    const int pb = (h * 16 + (qb - 16)) * 2;
    const float* o0 = g_po + (size_t)pb * 8192;
    const float* o1 = o0 + 8192;
    const float* ml0 = g_pml + (size_t)pb * 256;
    const float* ml1 = ml0 + 256;

    const int t = threadIdx.x;
    const int r = half * 64 + (t >> 2);    // 64 rows per block
    const int d0 = (t & 3) * 16;           // 16 floats per thread

    const float m0 = ml0[r], la = ml0[128 + r];
    const float m1 = ml1[r], lb = ml1[128 + r];
    const float m = fmaxf(m0, m1);
    const float w0 = ex2(m0 - m);
    const float w1 = ex2(m1 - m);
    const float linv = 1.0f / (la * w0 + lb * w1);

    float4 a[4], b[4];
#pragma unroll
    for (int j = 0; j < 4; j++) {
        a[j] = *(const float4*)&o0[r * 64 + d0 + j * 4];
        b[j] = *(const float4*)&o1[r * 64 + d0 + j * 4];
    }
    float* dst = g_ctx + (size_t)(qb * 128 + r) * DM + h * HD + d0;
#pragma unroll
    for (int j = 0; j < 4; j++) {
        float4 v;
        v.x = f2tff((a[j].x * w0 + b[j].x * w1) * linv);
        v.y = f2tff((a[j].y * w0 + b[j].y * w1) * linv);
        v.z = f2tff((a[j].z * w0 + b[j].z * w1) * linv);
        v.w = f2tff((a[j].w * w0 + b[j].w * w1) * linv);
        *(float4*)(dst + j * 4) = v;
    }
}

// ---------------------------------------------------------------------------
extern "C" void kernel_launch(void* const* d_in, const int* in_sizes, int n_in,
                              void* d_out, int out_size) {
    const float* x  = (const float*)d_in[0];
    const float* wq = (const float*)d_in[1];
    const float* wk = (const float*)d_in[2];
    const float* wv = (const float*)d_in[3];
    const float* wo = (const float*)d_in[4];
    const float* bo = (const float*)d_in[5];
    float* out = (float*)d_out;

    cudaFuncSetAttribute(flash_kernel, cudaFuncAttributeMaxDynamicSharedMemorySize,
                         FLASH_SMEM);
    cudaFuncSetAttribute(qkv_kernel, cudaFuncAttributeMaxDynamicSharedMemorySize,
                         GEMM_SMEM);
    cudaFuncSetAttribute(out_proj_kernel, cudaFuncAttributeMaxDynamicSharedMemorySize,
                         G64_SMEM);

    round_all_kernel<<<(NTOT4 + 255) / 256, 256>>>(x, wq, wk, wv, wo);
    qkv_kernel<<<dim3(DM / 128, SEQ / 128, 3), 256, GEMM_SMEM>>>();
    flash_kernel<<<dim3(48, NH), 256, FLASH_SMEM>>>();
    merge_kernel<<<dim3(32, NH), 256>>>();
    out_proj_kernel<<<dim3(DM / 128, SEQ / 64), 256, G64_SMEM>>>(bo, out);
}